// round 6
// baseline (speedup 1.0000x reference)
#include <cuda_runtime.h>
#include <math.h>

#define BATCH  32
#define NPTS   131072
#define TPB    256
#define N4     (NPTS / 4)                 // 32768 float4 per stream per batch
#define ITER   8                          // float4 per stream per thread
#define CHUNKS (N4 / (TPB * ITER))        // 16 blocks per batch

// per-(batch,chunk) 16 partial sums:
// [0]=W, [1..3]=Sum(w*xs), [4..6]=Sum(w*xt), [7..15]=Sum(w*xs_d*xt_e)
__device__ float g_part[BATCH][CHUNKS][16];
__device__ int   g_count[BATCH];          // zero-initialized; self-resetting per replay

__device__ __forceinline__ float det3f(const float R[3][3]) {
    return R[0][0] * (R[1][1] * R[2][2] - R[1][2] * R[2][1])
         - R[0][1] * (R[1][0] * R[2][2] - R[1][2] * R[2][0])
         + R[0][2] * (R[1][0] * R[2][1] - R[1][1] * R[2][0]);
}

// sqrt for x >= 0 via single MUFU (guarded against 0)
__device__ __forceinline__ float fsqrt_fast(float x) {
    x = fmaxf(x, 1e-30f);
    return x * rsqrtf(x);
}

__device__ void solve_batch(const float S[16], float* __restrict__ out, int b) {
    const float W = S[0];
    const float inv_denom = __fdividef(1.0f, W + 1e-6f);
    float cs[3], ct[3];
#pragma unroll
    for (int d = 0; d < 3; d++) {
        cs[d] = S[1 + d] * inv_denom;
        ct[d] = S[4 + d] * inv_denom;
    }

    // cov = M/denom - cs*ct^T * (2 - W/denom)
    const float f = 2.0f - W * inv_denom;
    float cov[3][3];
#pragma unroll
    for (int d = 0; d < 3; d++)
#pragma unroll
        for (int e = 0; e < 3; e++)
            cov[d][e] = S[7 + d * 3 + e] * inv_denom - cs[d] * ct[e] * f;

    // A = cov^T cov (symmetric PSD)
    float A[3][3];
#pragma unroll
    for (int i = 0; i < 3; i++)
#pragma unroll
        for (int j = 0; j < 3; j++) {
            float s = 0.0f;
#pragma unroll
            for (int k = 0; k < 3; k++) s += cov[k][i] * cov[k][j];
            A[i][j] = s;
        }

    float V[3][3] = {{1, 0, 0}, {0, 1, 0}, {0, 0, 1}};
    const int PP[3] = {0, 0, 1};
    const int QQ[3] = {1, 2, 2};
#pragma unroll
    for (int it = 0; it < 15; it++) {
        const int p = PP[it % 3], q = QQ[it % 3];
        const float apq = A[p][q];
        // relative guard: skip if off-diagonal is negligible vs diagonal
        if (fabsf(apq) > 1e-12f * (fabsf(A[p][p]) + fabsf(A[q][q]) + 1e-30f)) {
            const float theta = __fdividef(A[q][q] - A[p][p], 2.0f * apq);
            float tt;
            if (fabsf(theta) < 1e18f) {
                const float s2 = fmaf(theta, theta, 1.0f);   // finite
                const float hyp = s2 * rsqrtf(s2);           // sqrt(1+theta^2)
                tt = __fdividef((theta >= 0.0f ? 1.0f : -1.0f),
                                fabsf(theta) + hyp);
            } else {
                tt = __fdividef(0.5f, theta);                // asymptotic, ~0 (safe for inf)
            }
            const float c = rsqrtf(fmaf(tt, tt, 1.0f));
            const float s = tt * c;
#pragma unroll
            for (int k = 0; k < 3; k++) {
                float akp = A[k][p], akq = A[k][q];
                A[k][p] = c * akp - s * akq;
                A[k][q] = s * akp + c * akq;
            }
#pragma unroll
            for (int k = 0; k < 3; k++) {
                float apk = A[p][k], aqk = A[q][k];
                A[p][k] = c * apk - s * aqk;
                A[q][k] = s * apk + c * aqk;
            }
#pragma unroll
            for (int k = 0; k < 3; k++) {
                float vkp = V[k][p], vkq = V[k][q];
                V[k][p] = c * vkp - s * vkq;
                V[k][q] = s * vkp + c * vkq;
            }
        }
    }

    // sort eigenvalues descending, reorder V columns
    float eig[3] = {A[0][0], A[1][1], A[2][2]};
    int idx[3] = {0, 1, 2};
    for (int i = 0; i < 2; i++)
        for (int j = i + 1; j < 3; j++)
            if (eig[idx[j]] > eig[idx[i]]) { int tmp = idx[i]; idx[i] = idx[j]; idx[j] = tmp; }

    float Vc[3][3];
    float sv[3];
#pragma unroll
    for (int i = 0; i < 3; i++) {
        sv[i] = fsqrt_fast(fmaxf(eig[idx[i]], 0.0f));
#pragma unroll
        for (int k = 0; k < 3; k++) Vc[k][i] = V[k][idx[i]];
    }

    // U columns: u_i = cov * v_i / s_i
    float U[3][3];
    const float tiny = 1e-7f * (sv[0] > 0.0f ? sv[0] : 1.0f);
#pragma unroll
    for (int i = 0; i < 3; i++) {
        float u0 = 0, u1 = 0, u2 = 0;
#pragma unroll
        for (int j = 0; j < 3; j++) {
            u0 += cov[0][j] * Vc[j][i];
            u1 += cov[1][j] * Vc[j][i];
            u2 += cov[2][j] * Vc[j][i];
        }
        if (sv[i] > tiny) {
            float inv = __fdividef(1.0f, sv[i]);
            U[0][i] = u0 * inv; U[1][i] = u1 * inv; U[2][i] = u2 * inv;
        } else if (i == 2) {
            U[0][2] = U[1][0] * U[2][1] - U[2][0] * U[1][1];
            U[1][2] = U[2][0] * U[0][1] - U[0][0] * U[2][1];
            U[2][2] = U[0][0] * U[1][1] - U[1][0] * U[0][1];
        } else {
            U[0][i] = (i == 0); U[1][i] = (i == 1); U[2][i] = 0.0f;
        }
    }

    // rot_pos = V U^T
    float R[3][3];
#pragma unroll
    for (int r = 0; r < 3; r++)
#pragma unroll
        for (int c = 0; c < 3; c++) {
            float s = 0.0f;
#pragma unroll
            for (int i = 0; i < 3; i++) s += Vc[r][i] * U[c][i];
            R[r][c] = s;
        }

    if (!(det3f(R) > 0.0f)) {
#pragma unroll
        for (int r = 0; r < 3; r++)
#pragma unroll
            for (int c = 0; c < 3; c++)
                R[r][c] -= 2.0f * Vc[r][2] * U[c][2];
    }

    float tr[3];
#pragma unroll
    for (int r = 0; r < 3; r++)
        tr[r] = -(R[r][0] * cs[0] + R[r][1] * cs[1] + R[r][2] * cs[2]) + ct[r];

#pragma unroll
    for (int r = 0; r < 3; r++)
#pragma unroll
        for (int c = 0; c < 3; c++)
            out[b * 9 + r * 3 + c] = R[r][c];
#pragma unroll
    for (int r = 0; r < 3; r++)
        out[BATCH * 9 + b * 3 + r] = tr[r];
}

__global__ void __launch_bounds__(TPB) fused_kernel(
        const float* __restrict__ xyz_s,
        const float* __restrict__ weighted_t,
        const float* __restrict__ weights,
        const float* __restrict__ label,
        float* __restrict__ out) {
    const int b = blockIdx.y;
    const size_t base3 = (size_t)b * 3 * NPTS;
    const size_t base1 = (size_t)b * NPTS;

    const float4* xs0 = (const float4*)(xyz_s + base3);
    const float4* xs1 = (const float4*)(xyz_s + base3 + NPTS);
    const float4* xs2 = (const float4*)(xyz_s + base3 + 2 * NPTS);
    const float4* xt0 = (const float4*)(weighted_t + base3);
    const float4* xt1 = (const float4*)(weighted_t + base3 + NPTS);
    const float4* xt2 = (const float4*)(weighted_t + base3 + 2 * NPTS);
    const float4* wv  = (const float4*)(weights + base1);
    const float4* lv  = (const float4*)(label + base1);

    float a[16];
#pragma unroll
    for (int k = 0; k < 16; k++) a[k] = 0.0f;

    const int start = blockIdx.x * (TPB * ITER) + threadIdx.x;

#pragma unroll 1
    for (int j = 0; j < ITER; j++) {
        const int i = start + j * TPB;
        const float4 X0 = xs0[i];
        const float4 X1 = xs1[i];
        const float4 X2 = xs2[i];
        const float4 T0 = xt0[i];
        const float4 T1 = xt1[i];
        const float4 T2 = xt2[i];
        const float4 Wv = wv[i];
        const float4 Lv = lv[i];

#define LANE(c)                                                        \
        {                                                              \
            float w  = Wv.c * fabsf(Lv.c - 1.0f);                      \
            float x0 = X0.c, x1 = X1.c, x2 = X2.c;                     \
            float t0 = T0.c, t1 = T1.c, t2 = T2.c;                     \
            a[0] += w;                                                 \
            float w0 = w * x0, w1 = w * x1, w2 = w * x2;               \
            a[1] += w0; a[2] += w1; a[3] += w2;                        \
            a[4] += w * t0; a[5] += w * t1; a[6] += w * t2;            \
            a[7]  += w0 * t0; a[8]  += w0 * t1; a[9]  += w0 * t2;      \
            a[10] += w1 * t0; a[11] += w1 * t1; a[12] += w1 * t2;      \
            a[13] += w2 * t0; a[14] += w2 * t1; a[15] += w2 * t2;      \
        }
        LANE(x) LANE(y) LANE(z) LANE(w)
#undef LANE
    }

    // warp reduce
#pragma unroll
    for (int k = 0; k < 16; k++) {
#pragma unroll
        for (int off = 16; off > 0; off >>= 1)
            a[k] += __shfl_down_sync(0xffffffffu, a[k], off);
    }

    __shared__ float sred[TPB / 32][16];
    const int lane = threadIdx.x & 31;
    const int warp = threadIdx.x >> 5;
    if (lane == 0) {
#pragma unroll
        for (int k = 0; k < 16; k++) sred[warp][k] = a[k];
    }
    __syncthreads();

    __shared__ int is_last;
    if (threadIdx.x == 0) {
        float tmp[16];
#pragma unroll
        for (int k = 0; k < 16; k++) {
            float s = 0.0f;
#pragma unroll
            for (int w = 0; w < TPB / 32; w++) s += sred[w][k];
            tmp[k] = s;
        }
#pragma unroll
        for (int k = 0; k < 16; k++) g_part[b][blockIdx.x][k] = tmp[k];
        __threadfence();
        int old = atomicAdd(&g_count[b], 1);
        is_last = (old == CHUNKS - 1);
    }
    __syncthreads();

    if (!is_last) return;

    // last block of this batch: warp 0 reduces the CHUNKS=16 partials + solves
    if (warp != 0) return;
    __threadfence();  // acquire: make all g_part writes visible

    float acc[16];
    if (lane < CHUNKS) {
#pragma unroll
        for (int k = 0; k < 16; k++) acc[k] = g_part[b][lane][k];
    } else {
#pragma unroll
        for (int k = 0; k < 16; k++) acc[k] = 0.0f;
    }

#pragma unroll
    for (int k = 0; k < 16; k++) {
#pragma unroll
        for (int off = 8; off > 0; off >>= 1)
            acc[k] += __shfl_down_sync(0xffffffffu, acc[k], off);
    }

    if (lane == 0) {
        solve_batch(acc, out, b);
        g_count[b] = 0;   // reset for next graph replay
    }
}

extern "C" void kernel_launch(void* const* d_in, const int* in_sizes, int n_in,
                              void* d_out, int out_size) {
    const float* xyz_s      = (const float*)d_in[0];
    const float* weighted_t = (const float*)d_in[1];
    const float* weights    = (const float*)d_in[2];
    const float* label      = (const float*)d_in[3];
    float* out = (float*)d_out;

    dim3 grid(CHUNKS, BATCH);
    fused_kernel<<<grid, TPB>>>(xyz_s, weighted_t, weights, label, out);
}

// round 7
// speedup vs baseline: 1.0749x; 1.0749x over previous
#include <cuda_runtime.h>
#include <math.h>

#define BATCH  32
#define NPTS   131072
#define TPB    256
#define N4     (NPTS / 4)            // 32768 float4 per stream per batch
#define CHUNKS (N4 / TPB)            // 128 blocks per batch, 1 float4/thread/stream

// per-(batch,chunk) 16 partial sums:
// [0]=W, [1..3]=Sum(w*xs), [4..6]=Sum(w*xt), [7..15]=Sum(w*xs_d*xt_e)
__device__ float g_part[BATCH][CHUNKS][16];

__global__ void __launch_bounds__(TPB) reduce_kernel(
        const float* __restrict__ xyz_s,
        const float* __restrict__ weighted_t,
        const float* __restrict__ weights,
        const float* __restrict__ label) {
    const int b = blockIdx.y;
    const int i = blockIdx.x * TPB + threadIdx.x;   // float4 index within batch
    const size_t base3 = (size_t)b * 3 * NPTS;
    const size_t base1 = (size_t)b * NPTS;

    // 8 independent 128-bit loads, front-batched
    const float4 X0 = ((const float4*)(xyz_s + base3))[i];
    const float4 X1 = ((const float4*)(xyz_s + base3 + NPTS))[i];
    const float4 X2 = ((const float4*)(xyz_s + base3 + 2 * NPTS))[i];
    const float4 T0 = ((const float4*)(weighted_t + base3))[i];
    const float4 T1 = ((const float4*)(weighted_t + base3 + NPTS))[i];
    const float4 T2 = ((const float4*)(weighted_t + base3 + 2 * NPTS))[i];
    const float4 Wv = ((const float4*)(weights + base1))[i];
    const float4 Lv = ((const float4*)(label + base1))[i];

    float a[16];
#pragma unroll
    for (int k = 0; k < 16; k++) a[k] = 0.0f;

#define LANE(c)                                                        \
    {                                                                  \
        float w  = Wv.c * fabsf(Lv.c - 1.0f);                          \
        float x0 = X0.c, x1 = X1.c, x2 = X2.c;                         \
        float t0 = T0.c, t1 = T1.c, t2 = T2.c;                         \
        a[0] += w;                                                     \
        float w0 = w * x0, w1 = w * x1, w2 = w * x2;                   \
        a[1] += w0; a[2] += w1; a[3] += w2;                            \
        a[4] += w * t0; a[5] += w * t1; a[6] += w * t2;                \
        a[7]  += w0 * t0; a[8]  += w0 * t1; a[9]  += w0 * t2;          \
        a[10] += w1 * t0; a[11] += w1 * t1; a[12] += w1 * t2;          \
        a[13] += w2 * t0; a[14] += w2 * t1; a[15] += w2 * t2;          \
    }
    LANE(x) LANE(y) LANE(z) LANE(w)
#undef LANE

    // warp reduce
#pragma unroll
    for (int k = 0; k < 16; k++) {
#pragma unroll
        for (int off = 16; off > 0; off >>= 1)
            a[k] += __shfl_down_sync(0xffffffffu, a[k], off);
    }

    __shared__ float sred[TPB / 32][16];
    const int lane = threadIdx.x & 31;
    const int warp = threadIdx.x >> 5;
    if (lane == 0) {
#pragma unroll
        for (int k = 0; k < 16; k++) sred[warp][k] = a[k];
    }
    __syncthreads();

    if (warp == 0 && lane < 16) {
        float s = 0.0f;
#pragma unroll
        for (int w = 0; w < TPB / 32; w++) s += sred[w][lane];
        g_part[b][blockIdx.x][lane] = s;
    }
}

__device__ __forceinline__ float det3f(const float R[3][3]) {
    return R[0][0] * (R[1][1] * R[2][2] - R[1][2] * R[2][1])
         - R[0][1] * (R[1][0] * R[2][2] - R[1][2] * R[2][0])
         + R[0][2] * (R[1][0] * R[2][1] - R[1][1] * R[2][0]);
}

// sqrt for x >= 0 via single MUFU (guarded against 0)
__device__ __forceinline__ float fsqrt_fast(float x) {
    x = fmaxf(x, 1e-30f);
    return x * rsqrtf(x);
}

__device__ void solve_batch(const float S[16], float* __restrict__ out, int b) {
    const float W = S[0];
    const float inv_denom = __fdividef(1.0f, W + 1e-6f);
    float cs[3], ct[3];
#pragma unroll
    for (int d = 0; d < 3; d++) {
        cs[d] = S[1 + d] * inv_denom;
        ct[d] = S[4 + d] * inv_denom;
    }

    // cov = M/denom - cs*ct^T * (2 - W/denom)
    const float f = 2.0f - W * inv_denom;
    float cov[3][3];
#pragma unroll
    for (int d = 0; d < 3; d++)
#pragma unroll
        for (int e = 0; e < 3; e++)
            cov[d][e] = S[7 + d * 3 + e] * inv_denom - cs[d] * ct[e] * f;

    // A = cov^T cov (symmetric PSD)
    float A[3][3];
#pragma unroll
    for (int i = 0; i < 3; i++)
#pragma unroll
        for (int j = 0; j < 3; j++) {
            float s = 0.0f;
#pragma unroll
            for (int k = 0; k < 3; k++) s += cov[k][i] * cov[k][j];
            A[i][j] = s;
        }

    float V[3][3] = {{1, 0, 0}, {0, 1, 0}, {0, 0, 1}};
    const int PP[3] = {0, 0, 1};
    const int QQ[3] = {1, 2, 2};
#pragma unroll
    for (int it = 0; it < 15; it++) {
        const int p = PP[it % 3], q = QQ[it % 3];
        const float apq = A[p][q];
        // relative guard: skip if off-diagonal is negligible vs diagonal
        if (fabsf(apq) > 1e-12f * (fabsf(A[p][p]) + fabsf(A[q][q]) + 1e-30f)) {
            const float theta = __fdividef(A[q][q] - A[p][p], 2.0f * apq);
            float tt;
            if (fabsf(theta) < 1e18f) {
                const float s2 = fmaf(theta, theta, 1.0f);   // finite
                const float hyp = s2 * rsqrtf(s2);           // sqrt(1+theta^2)
                tt = __fdividef((theta >= 0.0f ? 1.0f : -1.0f),
                                fabsf(theta) + hyp);
            } else {
                tt = __fdividef(0.5f, theta);                // asymptotic, ~0 (safe for inf)
            }
            const float c = rsqrtf(fmaf(tt, tt, 1.0f));
            const float s = tt * c;
#pragma unroll
            for (int k = 0; k < 3; k++) {
                float akp = A[k][p], akq = A[k][q];
                A[k][p] = c * akp - s * akq;
                A[k][q] = s * akp + c * akq;
            }
#pragma unroll
            for (int k = 0; k < 3; k++) {
                float apk = A[p][k], aqk = A[q][k];
                A[p][k] = c * apk - s * aqk;
                A[q][k] = s * apk + c * aqk;
            }
#pragma unroll
            for (int k = 0; k < 3; k++) {
                float vkp = V[k][p], vkq = V[k][q];
                V[k][p] = c * vkp - s * vkq;
                V[k][q] = s * vkp + c * vkq;
            }
        }
    }

    // sort eigenvalues descending, reorder V columns
    float eig[3] = {A[0][0], A[1][1], A[2][2]};
    int idx[3] = {0, 1, 2};
    for (int i = 0; i < 2; i++)
        for (int j = i + 1; j < 3; j++)
            if (eig[idx[j]] > eig[idx[i]]) { int tmp = idx[i]; idx[i] = idx[j]; idx[j] = tmp; }

    float Vc[3][3];
    float sv[3];
#pragma unroll
    for (int i = 0; i < 3; i++) {
        sv[i] = fsqrt_fast(fmaxf(eig[idx[i]], 0.0f));
#pragma unroll
        for (int k = 0; k < 3; k++) Vc[k][i] = V[k][idx[i]];
    }

    // U columns: u_i = cov * v_i / s_i
    float U[3][3];
    const float tiny = 1e-7f * (sv[0] > 0.0f ? sv[0] : 1.0f);
#pragma unroll
    for (int i = 0; i < 3; i++) {
        float u0 = 0, u1 = 0, u2 = 0;
#pragma unroll
        for (int j = 0; j < 3; j++) {
            u0 += cov[0][j] * Vc[j][i];
            u1 += cov[1][j] * Vc[j][i];
            u2 += cov[2][j] * Vc[j][i];
        }
        if (sv[i] > tiny) {
            float inv = __fdividef(1.0f, sv[i]);
            U[0][i] = u0 * inv; U[1][i] = u1 * inv; U[2][i] = u2 * inv;
        } else if (i == 2) {
            U[0][2] = U[1][0] * U[2][1] - U[2][0] * U[1][1];
            U[1][2] = U[2][0] * U[0][1] - U[0][0] * U[2][1];
            U[2][2] = U[0][0] * U[1][1] - U[1][0] * U[0][1];
        } else {
            U[0][i] = (i == 0); U[1][i] = (i == 1); U[2][i] = 0.0f;
        }
    }

    // rot_pos = V U^T
    float R[3][3];
#pragma unroll
    for (int r = 0; r < 3; r++)
#pragma unroll
        for (int c = 0; c < 3; c++) {
            float s = 0.0f;
#pragma unroll
            for (int i = 0; i < 3; i++) s += Vc[r][i] * U[c][i];
            R[r][c] = s;
        }

    if (!(det3f(R) > 0.0f)) {
#pragma unroll
        for (int r = 0; r < 3; r++)
#pragma unroll
            for (int c = 0; c < 3; c++)
                R[r][c] -= 2.0f * Vc[r][2] * U[c][2];
    }

    float tr[3];
#pragma unroll
    for (int r = 0; r < 3; r++)
        tr[r] = -(R[r][0] * cs[0] + R[r][1] * cs[1] + R[r][2] * cs[2]) + ct[r];

#pragma unroll
    for (int r = 0; r < 3; r++)
#pragma unroll
        for (int c = 0; c < 3; c++)
            out[b * 9 + r * 3 + c] = R[r][c];
#pragma unroll
    for (int r = 0; r < 3; r++)
        out[BATCH * 9 + b * 3 + r] = tr[r];
}

// one block per batch: 128 threads reduce the 128 chunk-partials, thread 0 solves
__global__ void __launch_bounds__(CHUNKS) solve_kernel(float* __restrict__ out) {
    const int b = blockIdx.x;
    const int t = threadIdx.x;

    float a[16];
#pragma unroll
    for (int k = 0; k < 16; k++) a[k] = g_part[b][t][k];

#pragma unroll
    for (int k = 0; k < 16; k++) {
#pragma unroll
        for (int off = 16; off > 0; off >>= 1)
            a[k] += __shfl_down_sync(0xffffffffu, a[k], off);
    }

    __shared__ float sred[CHUNKS / 32][16];
    const int lane = t & 31;
    const int warp = t >> 5;
    if (lane == 0) {
#pragma unroll
        for (int k = 0; k < 16; k++) sred[warp][k] = a[k];
    }
    __syncthreads();

    if (t != 0) return;

    float S[16];
#pragma unroll
    for (int k = 0; k < 16; k++) {
        float s = 0.0f;
#pragma unroll
        for (int w = 0; w < CHUNKS / 32; w++) s += sred[w][k];
        S[k] = s;
    }

    solve_batch(S, out, b);
}

extern "C" void kernel_launch(void* const* d_in, const int* in_sizes, int n_in,
                              void* d_out, int out_size) {
    const float* xyz_s      = (const float*)d_in[0];
    const float* weighted_t = (const float*)d_in[1];
    const float* weights    = (const float*)d_in[2];
    const float* label      = (const float*)d_in[3];
    float* out = (float*)d_out;

    dim3 grid(CHUNKS, BATCH);
    reduce_kernel<<<grid, TPB>>>(xyz_s, weighted_t, weights, label);
    solve_kernel<<<BATCH, CHUNKS>>>(out);
}

// round 8
// speedup vs baseline: 1.1491x; 1.0691x over previous
#include <cuda_runtime.h>
#include <math.h>

#define BATCH  32
#define NPTS   131072
#define TPB    256
#define N4     (NPTS / 4)            // 32768 float4 per stream per batch
#define CHUNKS (N4 / TPB)            // 128 blocks per batch, 1 float4/thread/stream

// per-(batch,chunk) 16 partial sums:
// [0]=W, [1..3]=Sum(w*xs), [4..6]=Sum(w*xt), [7..15]=Sum(w*xs_d*xt_e)
__device__ float g_part[BATCH][CHUNKS][16];

__global__ void __launch_bounds__(TPB) reduce_kernel(
        const float* __restrict__ xyz_s,
        const float* __restrict__ weighted_t,
        const float* __restrict__ weights,
        const float* __restrict__ label) {
    const int b = blockIdx.y;
    const int i = blockIdx.x * TPB + threadIdx.x;   // float4 index within batch
    const size_t base3 = (size_t)b * 3 * NPTS;
    const size_t base1 = (size_t)b * NPTS;

    // 8 independent 128-bit loads, front-batched
    const float4 X0 = ((const float4*)(xyz_s + base3))[i];
    const float4 X1 = ((const float4*)(xyz_s + base3 + NPTS))[i];
    const float4 X2 = ((const float4*)(xyz_s + base3 + 2 * NPTS))[i];
    const float4 T0 = ((const float4*)(weighted_t + base3))[i];
    const float4 T1 = ((const float4*)(weighted_t + base3 + NPTS))[i];
    const float4 T2 = ((const float4*)(weighted_t + base3 + 2 * NPTS))[i];
    const float4 Wv = ((const float4*)(weights + base1))[i];
    const float4 Lv = ((const float4*)(label + base1))[i];

    float a[16];
#pragma unroll
    for (int k = 0; k < 16; k++) a[k] = 0.0f;

#define LANE(c)                                                        \
    {                                                                  \
        float w  = Wv.c * fabsf(Lv.c - 1.0f);                          \
        float x0 = X0.c, x1 = X1.c, x2 = X2.c;                         \
        float t0 = T0.c, t1 = T1.c, t2 = T2.c;                         \
        a[0] += w;                                                     \
        float w0 = w * x0, w1 = w * x1, w2 = w * x2;                   \
        a[1] += w0; a[2] += w1; a[3] += w2;                            \
        a[4] += w * t0; a[5] += w * t1; a[6] += w * t2;                \
        a[7]  += w0 * t0; a[8]  += w0 * t1; a[9]  += w0 * t2;          \
        a[10] += w1 * t0; a[11] += w1 * t1; a[12] += w1 * t2;          \
        a[13] += w2 * t0; a[14] += w2 * t1; a[15] += w2 * t2;          \
    }
    LANE(x) LANE(y) LANE(z) LANE(w)
#undef LANE

    // warp reduce
#pragma unroll
    for (int k = 0; k < 16; k++) {
#pragma unroll
        for (int off = 16; off > 0; off >>= 1)
            a[k] += __shfl_down_sync(0xffffffffu, a[k], off);
    }

    __shared__ float sred[TPB / 32][16];
    const int lane = threadIdx.x & 31;
    const int warp = threadIdx.x >> 5;
    if (lane == 0) {
#pragma unroll
        for (int k = 0; k < 16; k++) sred[warp][k] = a[k];
    }
    __syncthreads();

    if (warp == 0 && lane < 16) {
        float s = 0.0f;
#pragma unroll
        for (int w = 0; w < TPB / 32; w++) s += sred[w][lane];
        g_part[b][blockIdx.x][lane] = s;
    }
}

__device__ __forceinline__ float det3f(const float R[3][3]) {
    return R[0][0] * (R[1][1] * R[2][2] - R[1][2] * R[2][1])
         - R[0][1] * (R[1][0] * R[2][2] - R[1][2] * R[2][0])
         + R[0][2] * (R[1][0] * R[2][1] - R[1][1] * R[2][0]);
}

// sqrt for x >= 0 via single MUFU (guarded against 0)
__device__ __forceinline__ float fsqrt_fast(float x) {
    x = fmaxf(x, 1e-30f);
    return x * rsqrtf(x);
}

// unit eigenvector of symmetric A for eigenvalue lam, via largest cross product
// of rows of (A - lam I)
__device__ __forceinline__ void eigvec3(const float A[3][3], float lam, float v[3]) {
    const float m00 = A[0][0] - lam, m11 = A[1][1] - lam, m22 = A[2][2] - lam;
    const float m01 = A[0][1], m02 = A[0][2], m12 = A[1][2];
    // rows: r0=(m00,m01,m02) r1=(m01,m11,m12) r2=(m02,m12,m22)
    float c0[3] = { m01 * m12 - m02 * m11,   // r0 x r1
                    m02 * m01 - m00 * m12,
                    m00 * m11 - m01 * m01 };
    float c1[3] = { m01 * m22 - m02 * m12,   // r0 x r2
                    m02 * m02 - m00 * m22,
                    m00 * m12 - m01 * m02 };
    float c2[3] = { m11 * m22 - m12 * m12,   // r1 x r2
                    m12 * m02 - m01 * m22,
                    m01 * m12 - m11 * m02 };
    const float n0 = c0[0]*c0[0] + c0[1]*c0[1] + c0[2]*c0[2];
    const float n1 = c1[0]*c1[0] + c1[1]*c1[1] + c1[2]*c1[2];
    const float n2 = c2[0]*c2[0] + c2[1]*c2[1] + c2[2]*c2[2];
    const float* best = c0; float nb = n0;
    if (n1 > nb) { best = c1; nb = n1; }
    if (n2 > nb) { best = c2; nb = n2; }
    const float inv = rsqrtf(fmaxf(nb, 1e-30f));
    v[0] = best[0] * inv; v[1] = best[1] * inv; v[2] = best[2] * inv;
}

__device__ void solve_batch(const float S[16], float* __restrict__ out, int b) {
    const float W = S[0];
    const float inv_denom = __fdividef(1.0f, W + 1e-6f);
    float cs[3], ct[3];
#pragma unroll
    for (int d = 0; d < 3; d++) {
        cs[d] = S[1 + d] * inv_denom;
        ct[d] = S[4 + d] * inv_denom;
    }

    // cov = M/denom - cs*ct^T * (2 - W/denom)
    const float f = 2.0f - W * inv_denom;
    float cov[3][3];
#pragma unroll
    for (int d = 0; d < 3; d++)
#pragma unroll
        for (int e = 0; e < 3; e++)
            cov[d][e] = S[7 + d * 3 + e] * inv_denom - cs[d] * ct[e] * f;

    // A = cov^T cov (symmetric PSD)
    float A[3][3];
#pragma unroll
    for (int i = 0; i < 3; i++)
#pragma unroll
        for (int j = 0; j < 3; j++) {
            float s = 0.0f;
#pragma unroll
            for (int k = 0; k < 3; k++) s += cov[k][i] * cov[k][j];
            A[i][j] = s;
        }

    // ---- analytic eigendecomposition of A (eig0 >= eig1 >= eig2) ----
    float eig0, eig1, eig2;
    float v0[3], v1[3], v2[3];
    const float scale = fabsf(A[0][0]) + fabsf(A[1][1]) + fabsf(A[2][2]) + 1e-30f;
    const float q = (A[0][0] + A[1][1] + A[2][2]) * (1.0f / 3.0f);
    const float b00 = A[0][0] - q, b11 = A[1][1] - q, b22 = A[2][2] - q;
    const float a01 = A[0][1], a02 = A[0][2], a12 = A[1][2];
    const float p2 = b00 * b00 + b11 * b11 + b22 * b22
                   + 2.0f * (a01 * a01 + a02 * a02 + a12 * a12);

    if (p2 > 1e-14f * scale * scale) {
        const float p = fsqrt_fast(p2 * (1.0f / 6.0f));
        const float invp = __fdividef(1.0f, p);
        const float c00 = b00 * invp, c11 = b11 * invp, c22 = b22 * invp;
        const float c01 = a01 * invp, c02 = a02 * invp, c12 = a12 * invp;
        float detC = c00 * (c11 * c22 - c12 * c12)
                   - c01 * (c01 * c22 - c12 * c02)
                   + c02 * (c01 * c12 - c11 * c02);
        float r = 0.5f * detC;
        r = fminf(fmaxf(r, -1.0f), 1.0f);
        const float phi = acosf(r) * (1.0f / 3.0f);       // [0, pi/3]
        const float cphi = cosf(phi);
        const float sphi = fsqrt_fast(fmaxf(1.0f - cphi * cphi, 0.0f));
        eig0 = q + 2.0f * p * cphi;                                      // max
        eig2 = q + 2.0f * p * (-0.5f * cphi - 0.86602540f * sphi);       // min
        eig1 = 3.0f * q - eig0 - eig2;                                   // mid

        eigvec3(A, eig0, v0);
        eigvec3(A, eig2, v2);
        // mid eigenvector = cross(min, max) (orthogonal complement)
        v1[0] = v2[1] * v0[2] - v2[2] * v0[1];
        v1[1] = v2[2] * v0[0] - v2[0] * v0[2];
        v1[2] = v2[0] * v0[1] - v2[1] * v0[0];
        const float n1 = rsqrtf(fmaxf(v1[0]*v1[0] + v1[1]*v1[1] + v1[2]*v1[2], 1e-30f));
        v1[0] *= n1; v1[1] *= n1; v1[2] *= n1;
    } else {
        eig0 = eig1 = eig2 = q;
        v0[0] = 1; v0[1] = 0; v0[2] = 0;
        v1[0] = 0; v1[1] = 1; v1[2] = 0;
        v2[0] = 0; v2[1] = 0; v2[2] = 1;
    }

    float Vc[3][3];   // columns: v0 (max), v1 (mid), v2 (min)
#pragma unroll
    for (int k = 0; k < 3; k++) {
        Vc[k][0] = v0[k]; Vc[k][1] = v1[k]; Vc[k][2] = v2[k];
    }
    float sv[3];
    sv[0] = fsqrt_fast(fmaxf(eig0, 0.0f));
    sv[1] = fsqrt_fast(fmaxf(eig1, 0.0f));
    sv[2] = fsqrt_fast(fmaxf(eig2, 0.0f));

    // U columns: u_i = cov * v_i / s_i
    float U[3][3];
    const float tiny = 1e-7f * (sv[0] > 0.0f ? sv[0] : 1.0f);
#pragma unroll
    for (int i = 0; i < 3; i++) {
        float u0 = 0, u1 = 0, u2 = 0;
#pragma unroll
        for (int j = 0; j < 3; j++) {
            u0 += cov[0][j] * Vc[j][i];
            u1 += cov[1][j] * Vc[j][i];
            u2 += cov[2][j] * Vc[j][i];
        }
        if (sv[i] > tiny) {
            float inv = __fdividef(1.0f, sv[i]);
            U[0][i] = u0 * inv; U[1][i] = u1 * inv; U[2][i] = u2 * inv;
        } else if (i == 2) {
            U[0][2] = U[1][0] * U[2][1] - U[2][0] * U[1][1];
            U[1][2] = U[2][0] * U[0][1] - U[0][0] * U[2][1];
            U[2][2] = U[0][0] * U[1][1] - U[1][0] * U[0][1];
        } else {
            U[0][i] = (i == 0); U[1][i] = (i == 1); U[2][i] = 0.0f;
        }
    }

    // rot_pos = V U^T
    float R[3][3];
#pragma unroll
    for (int r = 0; r < 3; r++)
#pragma unroll
        for (int c = 0; c < 3; c++) {
            float s = 0.0f;
#pragma unroll
            for (int i = 0; i < 3; i++) s += Vc[r][i] * U[c][i];
            R[r][c] = s;
        }

    if (!(det3f(R) > 0.0f)) {
#pragma unroll
        for (int r = 0; r < 3; r++)
#pragma unroll
            for (int c = 0; c < 3; c++)
                R[r][c] -= 2.0f * Vc[r][2] * U[c][2];
    }

    float tr[3];
#pragma unroll
    for (int r = 0; r < 3; r++)
        tr[r] = -(R[r][0] * cs[0] + R[r][1] * cs[1] + R[r][2] * cs[2]) + ct[r];

#pragma unroll
    for (int r = 0; r < 3; r++)
#pragma unroll
        for (int c = 0; c < 3; c++)
            out[b * 9 + r * 3 + c] = R[r][c];
#pragma unroll
    for (int r = 0; r < 3; r++)
        out[BATCH * 9 + b * 3 + r] = tr[r];
}

// one block per batch: 128 threads reduce the 128 chunk-partials, thread 0 solves
__global__ void __launch_bounds__(CHUNKS) solve_kernel(float* __restrict__ out) {
    const int b = blockIdx.x;
    const int t = threadIdx.x;

    float a[16];
#pragma unroll
    for (int k = 0; k < 16; k++) a[k] = g_part[b][t][k];

#pragma unroll
    for (int k = 0; k < 16; k++) {
#pragma unroll
        for (int off = 16; off > 0; off >>= 1)
            a[k] += __shfl_down_sync(0xffffffffu, a[k], off);
    }

    __shared__ float sred[CHUNKS / 32][16];
    const int lane = t & 31;
    const int warp = t >> 5;
    if (lane == 0) {
#pragma unroll
        for (int k = 0; k < 16; k++) sred[warp][k] = a[k];
    }
    __syncthreads();

    if (t != 0) return;

    float S[16];
#pragma unroll
    for (int k = 0; k < 16; k++) {
        float s = 0.0f;
#pragma unroll
        for (int w = 0; w < CHUNKS / 32; w++) s += sred[w][k];
        S[k] = s;
    }

    solve_batch(S, out, b);
}

extern "C" void kernel_launch(void* const* d_in, const int* in_sizes, int n_in,
                              void* d_out, int out_size) {
    const float* xyz_s      = (const float*)d_in[0];
    const float* weighted_t = (const float*)d_in[1];
    const float* weights    = (const float*)d_in[2];
    const float* label      = (const float*)d_in[3];
    float* out = (float*)d_out;

    dim3 grid(CHUNKS, BATCH);
    reduce_kernel<<<grid, TPB>>>(xyz_s, weighted_t, weights, label);
    solve_kernel<<<BATCH, CHUNKS>>>(out);
}